// round 9
// baseline (speedup 1.0000x reference)
#include <cuda_runtime.h>
#include <math.h>
#include <stdint.h>

#define T_TOKENS 2048
#define HID 2048
#define NEXP 32
#define TOPK 8
#define INTER_SZ 768
#define NGU 1536
#define THRESH 0.8f

#define BM 128
#define TK 32
#define ROWF 36   // padded floats per smem row (32 + 4); 144B row stride

// ---------------- scratch (static device globals; no allocation) -------------
__device__ int   g_count[NEXP];
__device__ int   g_tokens[NEXP][T_TOKENS];
__device__ int   g_tok_nkeep[T_TOKENS];
__device__ int   g_tok_expert[T_TOKENS][TOPK];
__device__ int   g_tok_slot[T_TOKENS][TOPK];
__device__ float g_tok_w[T_TOKENS][TOPK];
__device__ __align__(128) float g_xcvt[T_TOKENS][HID];                 // tf32 bits of hidden
__device__ __align__(128) float g_h[NEXP][T_TOKENS][INTER_SZ];        // tf32 bits of silu(g)*u
__device__ __align__(128) float g_downbuf[(size_t)NEXP * T_TOKENS * HID];

// ---------------- helpers ----------------------------------------------------
__device__ __forceinline__ uint32_t cvt_tf32(float f) {
    uint32_t r;
    asm("cvt.rna.tf32.f32 %0, %1;" : "=r"(r) : "f"(f));
    return r;
}
__device__ __forceinline__ void cpasync16(uint32_t dst, const void* src) {
    asm volatile("cp.async.cg.shared.global [%0], [%1], 16;" :: "r"(dst), "l"(src));
}
__device__ __forceinline__ uint32_t smem_u32(const void* p) {
    uint32_t a;
    asm("{ .reg .u64 t; cvta.to.shared.u64 t, %1; cvt.u32.u64 %0, t; }" : "=r"(a) : "l"(p));
    return a;
}
__device__ __forceinline__ void ldsm4(uint32_t& r0, uint32_t& r1, uint32_t& r2, uint32_t& r3,
                                      uint32_t addr) {
    asm volatile("ldmatrix.sync.aligned.m8n8.x4.shared.b16 {%0,%1,%2,%3}, [%4];"
                 : "=r"(r0), "=r"(r1), "=r"(r2), "=r"(r3) : "r"(addr));
}
__device__ __forceinline__ void mma8(float* d, const uint32_t* a, const uint32_t* b) {
    asm volatile(
        "mma.sync.aligned.m16n8k8.row.col.f32.tf32.tf32.f32 "
        "{%0,%1,%2,%3}, {%4,%5,%6,%7}, {%8,%9}, {%0,%1,%2,%3};"
        : "+f"(d[0]), "+f"(d[1]), "+f"(d[2]), "+f"(d[3])
        : "r"(a[0]), "r"(a[1]), "r"(a[2]), "r"(a[3]), "r"(b[0]), "r"(b[1]));
}
__device__ __forceinline__ float silu(float g) {
    return g * (1.f / (1.f + __expf(-g)));
}

// ---------------- kernel 0: zero counts -------------------------------------
__global__ void zero_counts_kernel() {
    if (threadIdx.x < NEXP) g_count[threadIdx.x] = 0;
}

// ---------------- kernel 0b: pre-convert hidden to tf32 bits ----------------
__global__ void cvt_hidden_kernel(const float* __restrict__ x) {
    size_t i = (size_t)blockIdx.x * blockDim.x + threadIdx.x;   // float4 index
    float4 v = ((const float4*)x)[i];
    uint4 t;
    t.x = cvt_tf32(v.x); t.y = cvt_tf32(v.y);
    t.z = cvt_tf32(v.z); t.w = cvt_tf32(v.w);
    ((uint4*)g_xcvt)[i] = t;
}

// ---------------- kernel 1: router (fp32, reads raw hidden) ------------------
__global__ void router_kernel(const float* __restrict__ x,
                              const float* __restrict__ gw) {
    __shared__ float xs[HID];
    __shared__ float logits[NEXP];
    int t = blockIdx.x;
    const float* xp = x + (size_t)t * HID;
    for (int i = threadIdx.x; i < HID; i += blockDim.x) xs[i] = xp[i];
    __syncthreads();

    int warp = threadIdx.x >> 5, lane = threadIdx.x & 31;
    #pragma unroll
    for (int eo = 0; eo < 4; eo++) {
        int e = warp * 4 + eo;
        const float* w = gw + (size_t)e * HID;
        float s = 0.f;
        for (int j = lane; j < HID; j += 32) s += xs[j] * w[j];
        #pragma unroll
        for (int o = 16; o; o >>= 1) s += __shfl_xor_sync(0xffffffffu, s, o);
        if (lane == 0) logits[e] = s;
    }
    __syncthreads();

    if (threadIdx.x == 0) {
        float p[NEXP];
        float mx = -1e30f;
        #pragma unroll
        for (int e = 0; e < NEXP; e++) mx = fmaxf(mx, logits[e]);
        float sum = 0.f;
        #pragma unroll
        for (int e = 0; e < NEXP; e++) { p[e] = expf(logits[e] - mx); sum += p[e]; }
        float inv = 1.f / sum;
        #pragma unroll
        for (int e = 0; e < NEXP; e++) p[e] *= inv;

        float tv[TOPK]; int ti[TOPK];
        #pragma unroll
        for (int k = 0; k < TOPK; k++) {
            float best = -1.f; int bi = 0;
            #pragma unroll
            for (int e = 0; e < NEXP; e++)
                if (p[e] > best) { best = p[e]; bi = e; }
            tv[k] = best; ti[k] = bi; p[bi] = -1.f;
        }
        float s8 = 0.f;
        #pragma unroll
        for (int k = 0; k < TOPK; k++) s8 += tv[k];
        float invs8 = 1.f / fmaxf(s8, 1e-12f);
        float cum = 0.f; int cnt_lt = 0;
        #pragma unroll
        for (int k = 0; k < TOPK; k++) {
            cum += tv[k] * invs8;
            if (cum < THRESH) cnt_lt++;
        }
        int keep = min(cnt_lt + 1, TOPK);
        float ssel = 0.f;
        for (int k = 0; k < keep; k++) ssel += tv[k];
        float invsel = 1.f / fmaxf(ssel, 1e-12f);
        g_tok_nkeep[t] = keep;
        for (int k = 0; k < keep; k++) {
            int e = ti[k];
            int slot = atomicAdd(&g_count[e], 1);
            g_tokens[e][slot]   = t;
            g_tok_expert[t][k]  = e;
            g_tok_slot[t][k]    = slot;
            g_tok_w[t][k]       = tv[k] * invsel;
        }
    }
}

// ---------------- mma.sync tf32 grouped GEMM, 64x64 warp tiles ---------------
// 256 threads, 8 warps in 2(m) x 4(n). Warp tile M=64.
// FUSED=true : BN=128, warp N=32 for BOTH gate and up; writes tf32 silu(g)*u.
// FUSED=false: BN=256, warp N=64; writes fp32 to g_downbuf.
template<bool FUSED>
__global__ __launch_bounds__(256)
void moe_mma(const float* __restrict__ W) {
    constexpr int KDIM = FUSED ? HID : INTER_SZ;
    constexpr int NS   = KDIM / TK;              // 64 or 24
    constexpr int BNK  = FUSED ? 128 : 256;      // B rows per buffer tile
    constexpr int NJ   = FUSED ? 4 : 8;          // 8-col mma tiles per warp
    constexpr int NJ1  = FUSED ? 4 : 1;
    constexpr int WN   = FUSED ? 32 : 64;        // warp N extent (per matrix)
    constexpr int NBCH = FUSED ? 4 : 8;          // B float4 chunks per thread (B0[+B1])

    const int e   = blockIdx.z;
    const int cnt = g_count[e];
    const int m0  = blockIdx.y * BM;
    if (m0 >= cnt) return;
    const int n0  = blockIdx.x * BNK;

    extern __shared__ float smf[];
    int*  toks = (int*)(smf + 6 * BM * ROWF);    // after A+B buffers

    const int tid  = threadIdx.x;
    const int lane = tid & 31, wid = tid >> 5;
    const int warp_m = wid & 1, warp_n = wid >> 1;   // 2 x 4 warps

    if (FUSED && tid < BM) {
        int r = m0 + tid;
        toks[tid] = (r < cnt) ? g_tokens[e][r] : g_tokens[e][0];
    }
    __syncthreads();

    const uint32_t sa  = smem_u32(smf);
    const uint32_t aAs = sa;                                 // A: [2][128][ROWF]
    const uint32_t aB0 = sa + 2 * BM * ROWF * 4;             // B0: [2][BNK][ROWF]
    const uint32_t aB1 = aB0 + 2 * BNK * ROWF * 4;           // B1 (FUSED): [2][128][ROWF]

    const float* Wb = W + (size_t)e * (FUSED ? (size_t)NGU * HID : (size_t)HID * INTER_SZ)
                        + (size_t)n0 * KDIM;
    const float* Wu = FUSED ? (W + (size_t)e * NGU * HID + (size_t)(INTER_SZ + n0) * HID)
                            : (const float*)nullptr;

    // per-thread ldsm base offsets (bytes within a buffer)
    const int grp = lane >> 3, rr = lane & 7;
    const uint32_t abase = (uint32_t)(((warp_m * 64 + (grp & 1) * 8 + rr) * ROWF
                                       + (grp >> 1) * 4) * 4);
    const uint32_t bbase = (uint32_t)(((warp_n * WN + (grp >> 1) * 8 + rr) * ROWF
                                       + (grp & 1) * 4) * 4);

    // ---- A staging via cp.async (data already tf32 bits); 1024 chunks/256thr ----
    auto cpA = [&](int s) {
        const int buf = s & 1;
        const int k0  = s * TK;
        const uint32_t bufA = aAs + buf * BM * ROWF * 4;
        #pragma unroll
        for (int i = 0; i < 4; i++) {
            int c = tid + i * 256; int row = c >> 3, q = c & 7;
            const float* src;
            if (FUSED) {
                src = &g_xcvt[toks[row]][k0 + q * 4];
            } else {
                int r = m0 + row; if (r >= cnt) r = m0;
                src = &g_h[e][r][k0 + q * 4];
            }
            cpasync16(bufA + (row * ROWF + q * 4) * 4, src);
        }
        asm volatile("cp.async.commit_group;" ::: "memory");
    };

    // ---- B staging: LDG -> regs ----
    float4 vb[8];
    auto ldgB = [&](int s) {
        const int k0 = s * TK;
        #pragma unroll
        for (int i = 0; i < NBCH; i++) {
            int c = tid + i * 256; int row = c >> 3, q = c & 7;
            vb[i] = *(const float4*)(Wb + (size_t)row * KDIM + k0 + q * 4);
            if (FUSED)
                vb[i + NBCH] = *(const float4*)(Wu + (size_t)row * KDIM + k0 + q * 4);
        }
    };
    // ---- B staging: cvt + STS ----
    auto stsB = [&](int s) {
        const int buf = s & 1;
        #pragma unroll
        for (int i = 0; i < (FUSED ? 2 * NBCH : NBCH); i++) {
            uint4 t4;
            t4.x = cvt_tf32(vb[i].x); t4.y = cvt_tf32(vb[i].y);
            t4.z = cvt_tf32(vb[i].z); t4.w = cvt_tf32(vb[i].w);
            int c = tid + (i % NBCH) * 256; int row = c >> 3, q = c & 7;
            uint32_t base = (FUSED && i >= NBCH) ? aB1 : aB0;
            uint32_t off = (base - sa) + buf * BNK * ROWF * 4 + (row * ROWF + q * 4) * 4;
            *(uint4*)((char*)smf + off) = t4;
        }
    };

    float acc0[4][NJ][4] = {};
    float acc1[4][NJ1][4] = {};

    // ---- prologue ----
    ldgB(0); cpA(0);
    stsB(0);
    ldgB(1); cpA(1);
    asm volatile("cp.async.wait_group 1;" ::: "memory");
    __syncthreads();

    for (int s = 0; s < NS; s++) {
        const uint32_t bufA  = aAs + (s & 1) * BM * ROWF * 4;
        const uint32_t bufB0 = aB0 + (s & 1) * BNK * ROWF * 4;
        const uint32_t bufB1 = aB1 + (s & 1) * BNK * ROWF * 4;

        #pragma unroll
        for (int kk = 0; kk < 4; kk++) {
            uint32_t a[4][4];
            #pragma unroll
            for (int i = 0; i < 4; i++)
                ldsm4(a[i][0], a[i][1], a[i][2], a[i][3],
                      bufA + abase + i * 16 * ROWF * 4 + kk * 32);
            uint32_t b0[NJ][2];
            #pragma unroll
            for (int jp = 0; jp < NJ / 2; jp++)
                ldsm4(b0[2 * jp][0], b0[2 * jp][1], b0[2 * jp + 1][0], b0[2 * jp + 1][1],
                      bufB0 + bbase + jp * 16 * ROWF * 4 + kk * 32);
            uint32_t b1[NJ1][2];
            if (FUSED) {
                #pragma unroll
                for (int jp = 0; jp < NJ1 / 2; jp++)
                    ldsm4(b1[2 * jp][0], b1[2 * jp][1], b1[2 * jp + 1][0], b1[2 * jp + 1][1],
                          bufB1 + bbase + jp * 16 * ROWF * 4 + kk * 32);
            }
            #pragma unroll
            for (int i = 0; i < 4; i++)
                #pragma unroll
                for (int j = 0; j < NJ; j++) {
                    mma8(acc0[i][j], a[i], b0[j]);
                    if (FUSED) mma8(acc1[i][j % NJ1], a[i], b1[j % NJ1]);
                }
        }

        if (s + 1 < NS) {
            __syncthreads();
            stsB(s + 1);
            if (s + 2 < NS) { ldgB(s + 2); cpA(s + 2); }
            if (s + 2 < NS) asm volatile("cp.async.wait_group 1;" ::: "memory");
            else            asm volatile("cp.async.wait_group 0;" ::: "memory");
            __syncthreads();
        }
    }

    // ---- epilogue ----
    #pragma unroll
    for (int i = 0; i < 4; i++) {
        int r0 = m0 + warp_m * 64 + i * 16 + (lane >> 2);
        #pragma unroll
        for (int j = 0; j < NJ; j++) {
            int col = n0 + warp_n * WN + j * 8 + 2 * (lane & 3);
            if (FUSED) {
                if (r0 < cnt) {
                    float2 v;
                    v.x = __uint_as_float(cvt_tf32(silu(acc0[i][j][0]) * acc1[i][j % NJ1][0]));
                    v.y = __uint_as_float(cvt_tf32(silu(acc0[i][j][1]) * acc1[i][j % NJ1][1]));
                    *(float2*)&g_h[e][r0][col] = v;
                }
                if (r0 + 8 < cnt) {
                    float2 v;
                    v.x = __uint_as_float(cvt_tf32(silu(acc0[i][j][2]) * acc1[i][j % NJ1][2]));
                    v.y = __uint_as_float(cvt_tf32(silu(acc0[i][j][3]) * acc1[i][j % NJ1][3]));
                    *(float2*)&g_h[e][r0 + 8][col] = v;
                }
            } else {
                if (r0 < cnt) {
                    float2 v = make_float2(acc0[i][j][0], acc0[i][j][1]);
                    *(float2*)&g_downbuf[((size_t)e * T_TOKENS + r0) * HID + col] = v;
                }
                if (r0 + 8 < cnt) {
                    float2 v = make_float2(acc0[i][j][2], acc0[i][j][3]);
                    *(float2*)&g_downbuf[((size_t)e * T_TOKENS + r0 + 8) * HID + col] = v;
                }
            }
        }
    }
}

// ---------------- kernel 4: deterministic per-token combine -----------------
__global__ void combine_kernel(float* __restrict__ out) {
    int t = blockIdx.x;
    int nk = g_tok_nkeep[t];
    int   es[TOPK], ss[TOPK];
    float ws[TOPK];
    for (int k = 0; k < nk; k++) {
        es[k] = g_tok_expert[t][k];
        ss[k] = g_tok_slot[t][k];
        ws[k] = g_tok_w[t][k];
    }
    for (int h = threadIdx.x; h < HID; h += blockDim.x) {
        float acc = 0.f;
        for (int k = 0; k < nk; k++)
            acc += ws[k] * g_downbuf[((size_t)es[k] * T_TOKENS + ss[k]) * HID + h];
        out[(size_t)t * HID + h] = acc;
    }
}

// ---------------- launch ----------------------------------------------------
#define SMEM_BYTES ((6 * BM * ROWF + BM) * 4)   // 111104 B (both kernels)

extern "C" void kernel_launch(void* const* d_in, const int* in_sizes, int n_in,
                              void* d_out, int out_size) {
    const float* hidden  = (const float*)d_in[0];   // [2,1024,2048]
    const float* gate_w  = (const float*)d_in[1];   // [32,2048]
    const float* gate_up = (const float*)d_in[2];   // [32,1536,2048]
    const float* down_w  = (const float*)d_in[3];   // [32,2048,768]
    float* out = (float*)d_out;

    cudaFuncSetAttribute(moe_mma<true>,  cudaFuncAttributeMaxDynamicSharedMemorySize, SMEM_BYTES);
    cudaFuncSetAttribute(moe_mma<false>, cudaFuncAttributeMaxDynamicSharedMemorySize, SMEM_BYTES);

    zero_counts_kernel<<<1, 32>>>();
    cvt_hidden_kernel<<<(T_TOKENS * HID / 4) / 256, 256>>>(hidden);
    router_kernel<<<T_TOKENS, 256>>>(hidden, gate_w);
    {
        dim3 grid(INTER_SZ / 128, T_TOKENS / BM, NEXP);   // (6, 16, 32)
        moe_mma<true><<<grid, 256, SMEM_BYTES>>>(gate_up);
    }
    {
        dim3 grid(HID / 256, T_TOKENS / BM, NEXP);        // (8, 16, 32)
        moe_mma<false><<<grid, 256, SMEM_BYTES>>>(down_w);
    }
    combine_kernel<<<T_TOKENS, 256>>>(out);
}

// round 11
// speedup vs baseline: 1.7329x; 1.7329x over previous
#include <cuda_runtime.h>
#include <math.h>
#include <stdint.h>

#define T_TOKENS 2048
#define HID 2048
#define NEXP 32
#define TOPK 8
#define INTER_SZ 768
#define NGU 1536
#define THRESH 0.8f

#define BM 128
#define TK 32
#define ROWF 36   // padded floats per smem row (32 + 4); 144B row stride

// ---------------- scratch (static device globals; no allocation) -------------
__device__ int   g_count[NEXP];
__device__ int   g_tokens[NEXP][T_TOKENS];
__device__ int   g_tok_nkeep[T_TOKENS];
__device__ int   g_tok_expert[T_TOKENS][TOPK];
__device__ int   g_tok_slot[T_TOKENS][TOPK];
__device__ float g_tok_w[T_TOKENS][TOPK];
__device__ __align__(128) float g_xcvt[T_TOKENS][HID];                 // tf32 bits of hidden
__device__ __align__(128) float g_h[NEXP][T_TOKENS][INTER_SZ];        // tf32 bits of silu(g)*u
__device__ __align__(128) float g_downbuf[(size_t)NEXP * T_TOKENS * HID];

// ---------------- helpers ----------------------------------------------------
__device__ __forceinline__ uint32_t cvt_tf32(float f) {
    uint32_t r;
    asm("cvt.rna.tf32.f32 %0, %1;" : "=r"(r) : "f"(f));
    return r;
}
__device__ __forceinline__ void cpasync16(uint32_t dst, const void* src) {
    asm volatile("cp.async.cg.shared.global [%0], [%1], 16;" :: "r"(dst), "l"(src));
}
__device__ __forceinline__ uint32_t smem_u32(const void* p) {
    uint32_t a;
    asm("{ .reg .u64 t; cvta.to.shared.u64 t, %1; cvt.u32.u64 %0, t; }" : "=r"(a) : "l"(p));
    return a;
}
__device__ __forceinline__ void ldsm4(uint32_t& r0, uint32_t& r1, uint32_t& r2, uint32_t& r3,
                                      uint32_t addr) {
    asm volatile("ldmatrix.sync.aligned.m8n8.x4.shared.b16 {%0,%1,%2,%3}, [%4];"
                 : "=r"(r0), "=r"(r1), "=r"(r2), "=r"(r3) : "r"(addr));
}
__device__ __forceinline__ void mma8(float* d, const uint32_t* a, const uint32_t* b) {
    asm volatile(
        "mma.sync.aligned.m16n8k8.row.col.f32.tf32.tf32.f32 "
        "{%0,%1,%2,%3}, {%4,%5,%6,%7}, {%8,%9}, {%0,%1,%2,%3};"
        : "+f"(d[0]), "+f"(d[1]), "+f"(d[2]), "+f"(d[3])
        : "r"(a[0]), "r"(a[1]), "r"(a[2]), "r"(a[3]), "r"(b[0]), "r"(b[1]));
}
__device__ __forceinline__ float silu(float g) {
    return g * (1.f / (1.f + __expf(-g)));
}

// ---------------- kernel 0: zero counts -------------------------------------
__global__ void zero_counts_kernel() {
    if (threadIdx.x < NEXP) g_count[threadIdx.x] = 0;
}

// ---------------- kernel 0b: pre-convert hidden to tf32 bits ----------------
__global__ void cvt_hidden_kernel(const float* __restrict__ x) {
    size_t i = (size_t)blockIdx.x * blockDim.x + threadIdx.x;   // float4 index
    float4 v = ((const float4*)x)[i];
    uint4 t;
    t.x = cvt_tf32(v.x); t.y = cvt_tf32(v.y);
    t.z = cvt_tf32(v.z); t.w = cvt_tf32(v.w);
    ((uint4*)g_xcvt)[i] = t;
}

// ---------------- kernel 1: router (fp32, reads raw hidden) ------------------
__global__ void router_kernel(const float* __restrict__ x,
                              const float* __restrict__ gw) {
    __shared__ float xs[HID];
    __shared__ float logits[NEXP];
    int t = blockIdx.x;
    const float* xp = x + (size_t)t * HID;
    for (int i = threadIdx.x; i < HID; i += blockDim.x) xs[i] = xp[i];
    __syncthreads();

    int warp = threadIdx.x >> 5, lane = threadIdx.x & 31;
    #pragma unroll
    for (int eo = 0; eo < 4; eo++) {
        int e = warp * 4 + eo;
        const float* w = gw + (size_t)e * HID;
        float s = 0.f;
        for (int j = lane; j < HID; j += 32) s += xs[j] * w[j];
        #pragma unroll
        for (int o = 16; o; o >>= 1) s += __shfl_xor_sync(0xffffffffu, s, o);
        if (lane == 0) logits[e] = s;
    }
    __syncthreads();

    if (threadIdx.x == 0) {
        float p[NEXP];
        float mx = -1e30f;
        #pragma unroll
        for (int e = 0; e < NEXP; e++) mx = fmaxf(mx, logits[e]);
        float sum = 0.f;
        #pragma unroll
        for (int e = 0; e < NEXP; e++) { p[e] = expf(logits[e] - mx); sum += p[e]; }
        float inv = 1.f / sum;
        #pragma unroll
        for (int e = 0; e < NEXP; e++) p[e] *= inv;

        float tv[TOPK]; int ti[TOPK];
        #pragma unroll
        for (int k = 0; k < TOPK; k++) {
            float best = -1.f; int bi = 0;
            #pragma unroll
            for (int e = 0; e < NEXP; e++)
                if (p[e] > best) { best = p[e]; bi = e; }
            tv[k] = best; ti[k] = bi; p[bi] = -1.f;
        }
        float s8 = 0.f;
        #pragma unroll
        for (int k = 0; k < TOPK; k++) s8 += tv[k];
        float invs8 = 1.f / fmaxf(s8, 1e-12f);
        float cum = 0.f; int cnt_lt = 0;
        #pragma unroll
        for (int k = 0; k < TOPK; k++) {
            cum += tv[k] * invs8;
            if (cum < THRESH) cnt_lt++;
        }
        int keep = min(cnt_lt + 1, TOPK);
        float ssel = 0.f;
        for (int k = 0; k < keep; k++) ssel += tv[k];
        float invsel = 1.f / fmaxf(ssel, 1e-12f);
        g_tok_nkeep[t] = keep;
        for (int k = 0; k < keep; k++) {
            int e = ti[k];
            int slot = atomicAdd(&g_count[e], 1);
            g_tokens[e][slot]   = t;
            g_tok_expert[t][k]  = e;
            g_tok_slot[t][k]    = slot;
            g_tok_w[t][k]       = tv[k] * invsel;
        }
    }
}

// ---------------- mma.sync tf32 grouped GEMM, ldsm, single-barrier stages ----
// 512 threads, 16 warps in 4(m) x 4(n); warp tile M=32.
// A ring is 3-deep so cpA(s+2) never collides with stage-s readers; B is
// 2-deep (stsB(s+1) targets the buffer last read at s-1). One __syncthreads
// per stage => producer warps overlap consumer warps' mma.
// FUSED=true : BN=128, warp N=32 for gate AND up; writes tf32 silu(g)*u.
// FUSED=false: BN=256, warp N=64; writes fp32 to g_downbuf.
template<bool FUSED>
__global__ __launch_bounds__(512, 1)
void moe_mma(const float* __restrict__ W) {
    constexpr int KDIM = FUSED ? HID : INTER_SZ;
    constexpr int NS   = KDIM / TK;              // 64 or 24
    constexpr int BNK  = FUSED ? 128 : 256;      // B rows per buffer tile
    constexpr int NJ   = FUSED ? 4 : 8;          // 8-col mma tiles per warp
    constexpr int NJ1  = FUSED ? 4 : 1;
    constexpr int WN   = FUSED ? 32 : 64;        // warp N extent

    const int e   = blockIdx.z;
    const int cnt = g_count[e];
    const int m0  = blockIdx.y * BM;
    if (m0 >= cnt) return;
    const int n0  = blockIdx.x * BNK;

    extern __shared__ float smf[];
    int*  toks = (int*)(smf + 32256);            // after A(3) + B buffers

    const int tid  = threadIdx.x;
    const int lane = tid & 31, wid = tid >> 5;
    const int warp_m = wid & 3, warp_n = wid >> 2;           // 4 x 4 warps

    if (FUSED && tid < BM) {
        int r = m0 + tid;
        toks[tid] = (r < cnt) ? g_tokens[e][r] : g_tokens[e][0];
    }
    __syncthreads();

    const uint32_t sa  = smem_u32(smf);
    const uint32_t aAs = sa;                                 // A: [3][128][ROWF]
    const uint32_t aB0 = sa + 3 * BM * ROWF * 4;             // B0: [2][BNK][ROWF]
    const uint32_t aB1 = aB0 + 2 * BNK * ROWF * 4;           // B1 (FUSED): [2][128][ROWF]

    const float* Wb = W + (size_t)e * (FUSED ? (size_t)NGU * HID : (size_t)HID * INTER_SZ)
                        + (size_t)n0 * KDIM;
    const float* Wu = FUSED ? (W + (size_t)e * NGU * HID + (size_t)(INTER_SZ + n0) * HID)
                            : (const float*)nullptr;

    // per-thread ldsm base offsets (bytes within a buffer)
    const int grp = lane >> 3, rr = lane & 7;
    const uint32_t abase = (uint32_t)(((warp_m * 32 + (grp & 1) * 8 + rr) * ROWF
                                       + (grp >> 1) * 4) * 4);
    const uint32_t bbase = (uint32_t)(((warp_n * WN + (grp >> 1) * 8 + rr) * ROWF
                                       + (grp & 1) * 4) * 4);

    // ---- A staging via cp.async (data already tf32 bits); 3-deep ring ----
    auto cpA = [&](int s) {
        const int buf = s % 3;
        const int k0  = s * TK;
        const uint32_t bufA = aAs + buf * BM * ROWF * 4;
        #pragma unroll
        for (int i = 0; i < 2; i++) {
            int c = tid + i * 512; int row = c >> 3, q = c & 7;
            const float* src;
            if (FUSED) {
                src = &g_xcvt[toks[row]][k0 + q * 4];
            } else {
                int r = m0 + row; if (r >= cnt) r = m0;
                src = &g_h[e][r][k0 + q * 4];
            }
            cpasync16(bufA + (row * ROWF + q * 4) * 4, src);
        }
        asm volatile("cp.async.commit_group;" ::: "memory");
    };

    // ---- B staging: LDG -> regs ----
    float4 vb[4];
    auto ldgB = [&](int s) {
        const int k0 = s * TK;
        if (FUSED) {
            #pragma unroll
            for (int i = 0; i < 2; i++) {
                int c = tid + i * 512; int row = c >> 3, q = c & 7;
                vb[i]     = *(const float4*)(Wb + (size_t)row * KDIM + k0 + q * 4);
                vb[i + 2] = *(const float4*)(Wu + (size_t)row * KDIM + k0 + q * 4);
            }
        } else {
            #pragma unroll
            for (int i = 0; i < 4; i++) {
                int c = tid + i * 512; int row = c >> 3, q = c & 7;
                vb[i] = *(const float4*)(Wb + (size_t)row * KDIM + k0 + q * 4);
            }
        }
    };
    // ---- B staging: cvt + STS (2-deep) ----
    auto stsB = [&](int s) {
        const int buf = s & 1;
        #pragma unroll
        for (int i = 0; i < 4; i++) {
            uint4 t4;
            t4.x = cvt_tf32(vb[i].x); t4.y = cvt_tf32(vb[i].y);
            t4.z = cvt_tf32(vb[i].z); t4.w = cvt_tf32(vb[i].w);
            uint32_t off;
            if (FUSED) {
                int c = tid + (i & 1) * 512; int row = c >> 3, q = c & 7;
                uint32_t base = (i < 2) ? aB0 : aB1;
                off = (base - sa) + buf * BNK * ROWF * 4 + (row * ROWF + q * 4) * 4;
            } else {
                int c = tid + i * 512; int row = c >> 3, q = c & 7;
                off = (aB0 - sa) + buf * BNK * ROWF * 4 + (row * ROWF + q * 4) * 4;
            }
            *(uint4*)((char*)smf + off) = t4;
        }
    };

    float acc0[2][NJ][4] = {};
    float acc1[2][NJ1][4] = {};

    // ---- prologue ----
    ldgB(0); cpA(0);
    stsB(0);
    ldgB(1); cpA(1);
    asm volatile("cp.async.wait_group 1;" ::: "memory");
    __syncthreads();

    for (int s = 0; s < NS; s++) {
        const uint32_t bufA  = aAs + (s % 3) * BM * ROWF * 4;
        const uint32_t bufB0 = aB0 + (s & 1) * BNK * ROWF * 4;
        const uint32_t bufB1 = aB1 + (s & 1) * BNK * ROWF * 4;

        #pragma unroll
        for (int kk = 0; kk < 4; kk++) {
            uint32_t a[2][4];
            #pragma unroll
            for (int i = 0; i < 2; i++)
                ldsm4(a[i][0], a[i][1], a[i][2], a[i][3],
                      bufA + abase + i * 16 * ROWF * 4 + kk * 32);
            uint32_t b0[NJ][2];
            #pragma unroll
            for (int jp = 0; jp < NJ / 2; jp++)
                ldsm4(b0[2 * jp][0], b0[2 * jp][1], b0[2 * jp + 1][0], b0[2 * jp + 1][1],
                      bufB0 + bbase + jp * 16 * ROWF * 4 + kk * 32);
            uint32_t b1[NJ1][2];
            if (FUSED) {
                #pragma unroll
                for (int jp = 0; jp < NJ1 / 2; jp++)
                    ldsm4(b1[2 * jp][0], b1[2 * jp][1], b1[2 * jp + 1][0], b1[2 * jp + 1][1],
                          bufB1 + bbase + jp * 16 * ROWF * 4 + kk * 32);
            }
            #pragma unroll
            for (int i = 0; i < 2; i++)
                #pragma unroll
                for (int j = 0; j < NJ; j++) {
                    mma8(acc0[i][j], a[i], b0[j]);
                    if (FUSED) mma8(acc1[i][j % NJ1], a[i], b1[j % NJ1]);
                }
        }

        // single-barrier stage tail: producers overlap late consumers.
        // stsB(s+1) writes B buf (s+1)&1, last read at stage s-1 (fenced by the
        // barrier at end of s-1). cpA(s+2) writes A buf (s+2)%3 = (s-1)%3,
        // likewise fenced. No pre-producer barrier needed.
        if (s + 1 < NS) {
            stsB(s + 1);
            if (s + 2 < NS) { ldgB(s + 2); cpA(s + 2); }
            if (s + 2 < NS) asm volatile("cp.async.wait_group 1;" ::: "memory");
            else            asm volatile("cp.async.wait_group 0;" ::: "memory");
            __syncthreads();
        }
    }

    // ---- epilogue ----
    #pragma unroll
    for (int i = 0; i < 2; i++) {
        int r0 = m0 + warp_m * 32 + i * 16 + (lane >> 2);
        #pragma unroll
        for (int j = 0; j < NJ; j++) {
            int col = n0 + warp_n * WN + j * 8 + 2 * (lane & 3);
            if (FUSED) {
                if (r0 < cnt) {
                    float2 v;
                    v.x = __uint_as_float(cvt_tf32(silu(acc0[i][j][0]) * acc1[i][j % NJ1][0]));
                    v.y = __uint_as_float(cvt_tf32(silu(acc0[i][j][1]) * acc1[i][j % NJ1][1]));
                    *(float2*)&g_h[e][r0][col] = v;
                }
                if (r0 + 8 < cnt) {
                    float2 v;
                    v.x = __uint_as_float(cvt_tf32(silu(acc0[i][j][2]) * acc1[i][j % NJ1][2]));
                    v.y = __uint_as_float(cvt_tf32(silu(acc0[i][j][3]) * acc1[i][j % NJ1][3]));
                    *(float2*)&g_h[e][r0 + 8][col] = v;
                }
            } else {
                if (r0 < cnt) {
                    float2 v = make_float2(acc0[i][j][0], acc0[i][j][1]);
                    *(float2*)&g_downbuf[((size_t)e * T_TOKENS + r0) * HID + col] = v;
                }
                if (r0 + 8 < cnt) {
                    float2 v = make_float2(acc0[i][j][2], acc0[i][j][3]);
                    *(float2*)&g_downbuf[((size_t)e * T_TOKENS + r0 + 8) * HID + col] = v;
                }
            }
        }
    }
}

// ---------------- kernel 4: deterministic per-token combine -----------------
__global__ void combine_kernel(float* __restrict__ out) {
    int t = blockIdx.x;
    int nk = g_tok_nkeep[t];
    int   es[TOPK], ss[TOPK];
    float ws[TOPK];
    for (int k = 0; k < nk; k++) {
        es[k] = g_tok_expert[t][k];
        ss[k] = g_tok_slot[t][k];
        ws[k] = g_tok_w[t][k];
    }
    for (int h = threadIdx.x; h < HID; h += blockDim.x) {
        float acc = 0.f;
        for (int k = 0; k < nk; k++)
            acc += ws[k] * g_downbuf[((size_t)es[k] * T_TOKENS + ss[k]) * HID + h];
        out[(size_t)t * HID + h] = acc;
    }
}

// ---------------- launch ----------------------------------------------------
// A(3) + B(2x256 or 2x128+2x128) = 896 rows * ROWF floats + 128 ints
#define SMEM_BYTES (32256 * 4 + BM * 4)   // 129536 B (both kernels)

extern "C" void kernel_launch(void* const* d_in, const int* in_sizes, int n_in,
                              void* d_out, int out_size) {
    const float* hidden  = (const float*)d_in[0];   // [2,1024,2048]
    const float* gate_w  = (const float*)d_in[1];   // [32,2048]
    const float* gate_up = (const float*)d_in[2];   // [32,1536,2048]
    const float* down_w  = (const float*)d_in[3];   // [32,2048,768]
    float* out = (float*)d_out;

    cudaFuncSetAttribute(moe_mma<true>,  cudaFuncAttributeMaxDynamicSharedMemorySize, SMEM_BYTES);
    cudaFuncSetAttribute(moe_mma<false>, cudaFuncAttributeMaxDynamicSharedMemorySize, SMEM_BYTES);

    zero_counts_kernel<<<1, 32>>>();
    cvt_hidden_kernel<<<(T_TOKENS * HID / 4) / 256, 256>>>(hidden);
    router_kernel<<<T_TOKENS, 256>>>(hidden, gate_w);
    {
        dim3 grid(INTER_SZ / 128, T_TOKENS / BM, NEXP);   // (6, 16, 32)
        moe_mma<true><<<grid, 512, SMEM_BYTES>>>(gate_up);
    }
    {
        dim3 grid(HID / 256, T_TOKENS / BM, NEXP);        // (8, 16, 32)
        moe_mma<false><<<grid, 512, SMEM_BYTES>>>(down_w);
    }
    combine_kernel<<<T_TOKENS, 256>>>(out);
}

// round 12
// speedup vs baseline: 1.8785x; 1.0841x over previous
#include <cuda_runtime.h>
#include <math.h>
#include <stdint.h>

#define T_TOKENS 2048
#define HID 2048
#define NEXP 32
#define TOPK 8
#define INTER_SZ 768
#define NGU 1536
#define THRESH 0.8f

#define BM 128
#define TK 32
#define ROWF 36   // padded floats per smem row (32 + 4); 144B row stride

// ---------------- scratch (static device globals; no allocation) -------------
__device__ int   g_count[NEXP];
__device__ int   g_tokens[NEXP][T_TOKENS];
__device__ int   g_tok_nkeep[T_TOKENS];
__device__ int   g_tok_expert[T_TOKENS][TOPK];
__device__ int   g_tok_slot[T_TOKENS][TOPK];
__device__ float g_tok_w[T_TOKENS][TOPK];
__device__ __align__(128) float g_xcvt[T_TOKENS][HID];                 // tf32 bits of hidden
__device__ __align__(128) float g_h[NEXP][T_TOKENS][INTER_SZ];        // tf32 bits of silu(g)*u
__device__ __align__(128) float g_downbuf[(size_t)NEXP * T_TOKENS * HID];

// ---------------- helpers ----------------------------------------------------
__device__ __forceinline__ uint32_t cvt_tf32(float f) {
    uint32_t r;
    asm("cvt.rna.tf32.f32 %0, %1;" : "=r"(r) : "f"(f));
    return r;
}
__device__ __forceinline__ void cpasync16(uint32_t dst, const void* src) {
    asm volatile("cp.async.cg.shared.global [%0], [%1], 16;" :: "r"(dst), "l"(src));
}
__device__ __forceinline__ uint32_t smem_u32(const void* p) {
    uint32_t a;
    asm("{ .reg .u64 t; cvta.to.shared.u64 t, %1; cvt.u32.u64 %0, t; }" : "=r"(a) : "l"(p));
    return a;
}
__device__ __forceinline__ void ldsm4(uint32_t& r0, uint32_t& r1, uint32_t& r2, uint32_t& r3,
                                      uint32_t addr) {
    asm volatile("ldmatrix.sync.aligned.m8n8.x4.shared.b16 {%0,%1,%2,%3}, [%4];"
                 : "=r"(r0), "=r"(r1), "=r"(r2), "=r"(r3) : "r"(addr));
}
__device__ __forceinline__ void mma8(float* d, const uint32_t* a, const uint32_t* b) {
    asm volatile(
        "mma.sync.aligned.m16n8k8.row.col.f32.tf32.tf32.f32 "
        "{%0,%1,%2,%3}, {%4,%5,%6,%7}, {%8,%9}, {%0,%1,%2,%3};"
        : "+f"(d[0]), "+f"(d[1]), "+f"(d[2]), "+f"(d[3])
        : "r"(a[0]), "r"(a[1]), "r"(a[2]), "r"(a[3]), "r"(b[0]), "r"(b[1]));
}
__device__ __forceinline__ float silu(float g) {
    return g * (1.f / (1.f + __expf(-g)));
}

// ---------------- kernel 0: zero counts -------------------------------------
__global__ void zero_counts_kernel() {
    if (threadIdx.x < NEXP) g_count[threadIdx.x] = 0;
}

// ---------------- kernel 0b: pre-convert hidden to tf32 bits ----------------
__global__ void cvt_hidden_kernel(const float* __restrict__ x) {
    size_t i = (size_t)blockIdx.x * blockDim.x + threadIdx.x;   // float4 index
    float4 v = ((const float4*)x)[i];
    uint4 t;
    t.x = cvt_tf32(v.x); t.y = cvt_tf32(v.y);
    t.z = cvt_tf32(v.z); t.w = cvt_tf32(v.w);
    ((uint4*)g_xcvt)[i] = t;
}

// ---------------- kernel 1: router (fp32, reads raw hidden) ------------------
__global__ void router_kernel(const float* __restrict__ x,
                              const float* __restrict__ gw) {
    __shared__ float xs[HID];
    __shared__ float logits[NEXP];
    int t = blockIdx.x;
    const float* xp = x + (size_t)t * HID;
    for (int i = threadIdx.x; i < HID; i += blockDim.x) xs[i] = xp[i];
    __syncthreads();

    int warp = threadIdx.x >> 5, lane = threadIdx.x & 31;
    #pragma unroll
    for (int eo = 0; eo < 4; eo++) {
        int e = warp * 4 + eo;
        const float* w = gw + (size_t)e * HID;
        float s = 0.f;
        for (int j = lane; j < HID; j += 32) s += xs[j] * w[j];
        #pragma unroll
        for (int o = 16; o; o >>= 1) s += __shfl_xor_sync(0xffffffffu, s, o);
        if (lane == 0) logits[e] = s;
    }
    __syncthreads();

    if (threadIdx.x == 0) {
        float p[NEXP];
        float mx = -1e30f;
        #pragma unroll
        for (int e = 0; e < NEXP; e++) mx = fmaxf(mx, logits[e]);
        float sum = 0.f;
        #pragma unroll
        for (int e = 0; e < NEXP; e++) { p[e] = expf(logits[e] - mx); sum += p[e]; }
        float inv = 1.f / sum;
        #pragma unroll
        for (int e = 0; e < NEXP; e++) p[e] *= inv;

        float tv[TOPK]; int ti[TOPK];
        #pragma unroll
        for (int k = 0; k < TOPK; k++) {
            float best = -1.f; int bi = 0;
            #pragma unroll
            for (int e = 0; e < NEXP; e++)
                if (p[e] > best) { best = p[e]; bi = e; }
            tv[k] = best; ti[k] = bi; p[bi] = -1.f;
        }
        float s8 = 0.f;
        #pragma unroll
        for (int k = 0; k < TOPK; k++) s8 += tv[k];
        float invs8 = 1.f / fmaxf(s8, 1e-12f);
        float cum = 0.f; int cnt_lt = 0;
        #pragma unroll
        for (int k = 0; k < TOPK; k++) {
            cum += tv[k] * invs8;
            if (cum < THRESH) cnt_lt++;
        }
        int keep = min(cnt_lt + 1, TOPK);
        float ssel = 0.f;
        for (int k = 0; k < keep; k++) ssel += tv[k];
        float invsel = 1.f / fmaxf(ssel, 1e-12f);
        g_tok_nkeep[t] = keep;
        for (int k = 0; k < keep; k++) {
            int e = ti[k];
            int slot = atomicAdd(&g_count[e], 1);
            g_tokens[e][slot]   = t;
            g_tok_expert[t][k]  = e;
            g_tok_slot[t][k]    = slot;
            g_tok_w[t][k]       = tv[k] * invsel;
        }
    }
}

// ---------------- mma.sync tf32 grouped GEMM, 256thr x 2 CTAs/SM -------------
// 8 warps in 4(m) x 2(n); warp tile 32 x (32|64). A ring 3-deep, B 2-deep,
// single __syncthreads per stage (R11 scheme). Smem 92.7KB -> 2 CTAs/SM.
// FUSED=true : BN=64 per matrix (gate+up), writes tf32 silu(g)*u to g_h.
// FUSED=false: BN=128, writes fp32 to g_downbuf.
template<bool FUSED>
__global__ __launch_bounds__(256, 2)
void moe_mma(const float* __restrict__ W) {
    constexpr int KDIM = FUSED ? HID : INTER_SZ;
    constexpr int NS   = KDIM / TK;              // 64 or 24
    constexpr int BNK  = FUSED ? 64 : 128;       // B rows per matrix tile
    constexpr int NJ   = FUSED ? 4 : 8;          // 8-col mma tiles per warp
    constexpr int NJ1  = FUSED ? 4 : 1;
    constexpr int WN   = FUSED ? 32 : 64;        // warp N extent
    constexpr int NB   = FUSED ? 2 : 4;          // B0 float4 chunks per thread

    const int e   = blockIdx.z;
    const int cnt = g_count[e];
    const int m0  = blockIdx.y * BM;
    if (m0 >= cnt) return;
    const int n0  = blockIdx.x * BNK;

    extern __shared__ float smf[];
    int*  toks = (int*)(smf + 23040);            // after A(3) + B buffers

    const int tid  = threadIdx.x;
    const int lane = tid & 31, wid = tid >> 5;
    const int warp_m = wid & 3, warp_n = wid >> 2;           // 4 x 2 warps

    if (FUSED && tid < BM) {
        int r = m0 + tid;
        toks[tid] = (r < cnt) ? g_tokens[e][r] : g_tokens[e][0];
    }
    __syncthreads();

    const uint32_t sa  = smem_u32(smf);
    const uint32_t aAs = sa;                                 // A: [3][128][ROWF]
    const uint32_t aB0 = sa + 3 * BM * ROWF * 4;             // B0: [2][BNK][ROWF]
    const uint32_t aB1 = aB0 + 2 * BNK * ROWF * 4;           // B1 (FUSED): [2][64][ROWF]

    const float* Wb = W + (size_t)e * (FUSED ? (size_t)NGU * HID : (size_t)HID * INTER_SZ)
                        + (size_t)n0 * KDIM;
    const float* Wu = FUSED ? (W + (size_t)e * NGU * HID + (size_t)(INTER_SZ + n0) * HID)
                            : (const float*)nullptr;

    // per-thread ldsm base offsets (bytes within a buffer)
    const int grp = lane >> 3, rr = lane & 7;
    const uint32_t abase = (uint32_t)(((warp_m * 32 + (grp & 1) * 8 + rr) * ROWF
                                       + (grp >> 1) * 4) * 4);
    const uint32_t bbase = (uint32_t)(((warp_n * WN + (grp >> 1) * 8 + rr) * ROWF
                                       + (grp & 1) * 4) * 4);

    // ---- A staging via cp.async (data already tf32 bits); 3-deep ring ----
    auto cpA = [&](int s) {
        const int buf = s % 3;
        const int k0  = s * TK;
        const uint32_t bufA = aAs + buf * BM * ROWF * 4;
        #pragma unroll
        for (int i = 0; i < 4; i++) {                        // 1024 chunks / 256 thr
            int c = tid + i * 256; int row = c >> 3, q = c & 7;
            const float* src;
            if (FUSED) {
                src = &g_xcvt[toks[row]][k0 + q * 4];
            } else {
                int r = m0 + row; if (r >= cnt) r = m0;
                src = &g_h[e][r][k0 + q * 4];
            }
            cpasync16(bufA + (row * ROWF + q * 4) * 4, src);
        }
        asm volatile("cp.async.commit_group;" ::: "memory");
    };

    // ---- B staging: LDG -> regs ----
    float4 vb[4];
    auto ldgB = [&](int s) {
        const int k0 = s * TK;
        #pragma unroll
        for (int i = 0; i < NB; i++) {
            int c = tid + i * 256; int row = c >> 3, q = c & 7;
            vb[i] = *(const float4*)(Wb + (size_t)row * KDIM + k0 + q * 4);
            if (FUSED)
                vb[i + 2] = *(const float4*)(Wu + (size_t)row * KDIM + k0 + q * 4);
        }
    };
    // ---- B staging: cvt + STS (2-deep) ----
    auto stsB = [&](int s) {
        const int buf = s & 1;
        #pragma unroll
        for (int i = 0; i < 4; i++) {
            uint4 t4;
            t4.x = cvt_tf32(vb[i].x); t4.y = cvt_tf32(vb[i].y);
            t4.z = cvt_tf32(vb[i].z); t4.w = cvt_tf32(vb[i].w);
            uint32_t off;
            if (FUSED) {
                int c = tid + (i & 1) * 256; int row = c >> 3, q = c & 7;
                uint32_t base = (i < 2) ? aB0 : aB1;
                off = (base - sa) + buf * BNK * ROWF * 4 + (row * ROWF + q * 4) * 4;
            } else {
                int c = tid + i * 256; int row = c >> 3, q = c & 7;
                off = (aB0 - sa) + buf * BNK * ROWF * 4 + (row * ROWF + q * 4) * 4;
            }
            *(uint4*)((char*)smf + off) = t4;
        }
    };

    float acc0[2][NJ][4] = {};
    float acc1[2][NJ1][4] = {};

    // ---- prologue ----
    ldgB(0); cpA(0);
    stsB(0);
    ldgB(1); cpA(1);
    asm volatile("cp.async.wait_group 1;" ::: "memory");
    __syncthreads();

    for (int s = 0; s < NS; s++) {
        const uint32_t bufA  = aAs + (s % 3) * BM * ROWF * 4;
        const uint32_t bufB0 = aB0 + (s & 1) * BNK * ROWF * 4;
        const uint32_t bufB1 = aB1 + (s & 1) * BNK * ROWF * 4;

        #pragma unroll
        for (int kk = 0; kk < 4; kk++) {
            uint32_t a[2][4];
            #pragma unroll
            for (int i = 0; i < 2; i++)
                ldsm4(a[i][0], a[i][1], a[i][2], a[i][3],
                      bufA + abase + i * 16 * ROWF * 4 + kk * 32);
            uint32_t b0[NJ][2];
            #pragma unroll
            for (int jp = 0; jp < NJ / 2; jp++)
                ldsm4(b0[2 * jp][0], b0[2 * jp][1], b0[2 * jp + 1][0], b0[2 * jp + 1][1],
                      bufB0 + bbase + jp * 16 * ROWF * 4 + kk * 32);
            uint32_t b1[NJ1][2];
            if (FUSED) {
                #pragma unroll
                for (int jp = 0; jp < NJ1 / 2; jp++)
                    ldsm4(b1[2 * jp][0], b1[2 * jp][1], b1[2 * jp + 1][0], b1[2 * jp + 1][1],
                          bufB1 + bbase + jp * 16 * ROWF * 4 + kk * 32);
            }
            #pragma unroll
            for (int i = 0; i < 2; i++)
                #pragma unroll
                for (int j = 0; j < NJ; j++) {
                    mma8(acc0[i][j], a[i], b0[j]);
                    if (FUSED) mma8(acc1[i][j % NJ1], a[i], b1[j % NJ1]);
                }
        }

        // single-barrier stage tail (see R11): stsB(s+1)->B buf (s+1)&1 last
        // read at s-1; cpA(s+2)->A buf (s-1)%3 last read at s-1. Both fenced
        // by the barrier that ended stage s-1.
        if (s + 1 < NS) {
            stsB(s + 1);
            if (s + 2 < NS) { ldgB(s + 2); cpA(s + 2); }
            if (s + 2 < NS) asm volatile("cp.async.wait_group 1;" ::: "memory");
            else            asm volatile("cp.async.wait_group 0;" ::: "memory");
            __syncthreads();
        }
    }

    // ---- epilogue ----
    #pragma unroll
    for (int i = 0; i < 2; i++) {
        int r0 = m0 + warp_m * 32 + i * 16 + (lane >> 2);
        #pragma unroll
        for (int j = 0; j < NJ; j++) {
            int col = n0 + warp_n * WN + j * 8 + 2 * (lane & 3);
            if (FUSED) {
                if (r0 < cnt) {
                    float2 v;
                    v.x = __uint_as_float(cvt_tf32(silu(acc0[i][j][0]) * acc1[i][j % NJ1][0]));
                    v.y = __uint_as_float(cvt_tf32(silu(acc0[i][j][1]) * acc1[i][j % NJ1][1]));
                    *(float2*)&g_h[e][r0][col] = v;
                }
                if (r0 + 8 < cnt) {
                    float2 v;
                    v.x = __uint_as_float(cvt_tf32(silu(acc0[i][j][2]) * acc1[i][j % NJ1][2]));
                    v.y = __uint_as_float(cvt_tf32(silu(acc0[i][j][3]) * acc1[i][j % NJ1][3]));
                    *(float2*)&g_h[e][r0 + 8][col] = v;
                }
            } else {
                if (r0 < cnt) {
                    float2 v = make_float2(acc0[i][j][0], acc0[i][j][1]);
                    *(float2*)&g_downbuf[((size_t)e * T_TOKENS + r0) * HID + col] = v;
                }
                if (r0 + 8 < cnt) {
                    float2 v = make_float2(acc0[i][j][2], acc0[i][j][3]);
                    *(float2*)&g_downbuf[((size_t)e * T_TOKENS + r0 + 8) * HID + col] = v;
                }
            }
        }
    }
}

// ---------------- kernel 4: deterministic per-token combine -----------------
__global__ void combine_kernel(float* __restrict__ out) {
    int t = blockIdx.x;
    int nk = g_tok_nkeep[t];
    int   es[TOPK], ss[TOPK];
    float ws[TOPK];
    for (int k = 0; k < nk; k++) {
        es[k] = g_tok_expert[t][k];
        ss[k] = g_tok_slot[t][k];
        ws[k] = g_tok_w[t][k];
    }
    for (int h = threadIdx.x; h < HID; h += blockDim.x) {
        float acc = 0.f;
        for (int k = 0; k < nk; k++)
            acc += ws[k] * g_downbuf[((size_t)es[k] * T_TOKENS + ss[k]) * HID + h];
        out[(size_t)t * HID + h] = acc;
    }
}

// ---------------- launch ----------------------------------------------------
// A(3x128) + B(2x128 total rows) = 640 rows * ROWF floats = 23040 floats
#define SMEM_BYTES (23040 * 4 + BM * 4)   // 92672 B; 2 CTAs/SM

extern "C" void kernel_launch(void* const* d_in, const int* in_sizes, int n_in,
                              void* d_out, int out_size) {
    const float* hidden  = (const float*)d_in[0];   // [2,1024,2048]
    const float* gate_w  = (const float*)d_in[1];   // [32,2048]
    const float* gate_up = (const float*)d_in[2];   // [32,1536,2048]
    const float* down_w  = (const float*)d_in[3];   // [32,2048,768]
    float* out = (float*)d_out;

    cudaFuncSetAttribute(moe_mma<true>,  cudaFuncAttributeMaxDynamicSharedMemorySize, SMEM_BYTES);
    cudaFuncSetAttribute(moe_mma<false>, cudaFuncAttributeMaxDynamicSharedMemorySize, SMEM_BYTES);

    zero_counts_kernel<<<1, 32>>>();
    cvt_hidden_kernel<<<(T_TOKENS * HID / 4) / 256, 256>>>(hidden);
    router_kernel<<<T_TOKENS, 256>>>(hidden, gate_w);
    {
        dim3 grid(INTER_SZ / 64, T_TOKENS / BM, NEXP);    // (12, 16, 32)
        moe_mma<true><<<grid, 256, SMEM_BYTES>>>(gate_up);
    }
    {
        dim3 grid(HID / 128, T_TOKENS / BM, NEXP);        // (16, 16, 32)
        moe_mma<false><<<grid, 256, SMEM_BYTES>>>(down_w);
    }
    combine_kernel<<<T_TOKENS, 256>>>(out);
}

// round 13
// speedup vs baseline: 2.0967x; 1.1161x over previous
#include <cuda_runtime.h>
#include <math.h>
#include <stdint.h>

#define T_TOKENS 2048
#define HID 2048
#define NEXP 32
#define TOPK 8
#define INTER_SZ 768
#define NGU 1536
#define THRESH 0.8f
#define LAMBDA 1.000345f   // compensation for tf32 RZ-truncation of B operands

#define BM 128
#define TK 32
#define ROWF 36   // padded floats per smem row (32 + 4); 144B row stride

// ---------------- scratch (static device globals; no allocation) -------------
__device__ int   g_count[NEXP];
__device__ int   g_tokens[NEXP][T_TOKENS];
__device__ int   g_tok_nkeep[T_TOKENS];
__device__ int   g_tok_expert[T_TOKENS][TOPK];
__device__ int   g_tok_slot[T_TOKENS][TOPK];
__device__ float g_tok_w[T_TOKENS][TOPK];
__device__ __align__(128) float g_xcvt[T_TOKENS][HID];                 // RNA(lambda * x)
__device__ __align__(128) float g_h[NEXP][T_TOKENS][INTER_SZ];        // RNA(lambda * silu(g)*u)
__device__ __align__(128) float g_downbuf[(size_t)NEXP * T_TOKENS * HID];

// ---------------- helpers ----------------------------------------------------
__device__ __forceinline__ uint32_t cvt_tf32(float f) {
    uint32_t r;
    asm("cvt.rna.tf32.f32 %0, %1;" : "=r"(r) : "f"(f));
    return r;
}
__device__ __forceinline__ void cpasync16(uint32_t dst, const void* src) {
    asm volatile("cp.async.cg.shared.global [%0], [%1], 16;" :: "r"(dst), "l"(src));
}
__device__ __forceinline__ uint32_t smem_u32(const void* p) {
    uint32_t a;
    asm("{ .reg .u64 t; cvta.to.shared.u64 t, %1; cvt.u32.u64 %0, t; }" : "=r"(a) : "l"(p));
    return a;
}
__device__ __forceinline__ void ldsm4(uint32_t& r0, uint32_t& r1, uint32_t& r2, uint32_t& r3,
                                      uint32_t addr) {
    asm volatile("ldmatrix.sync.aligned.m8n8.x4.shared.b16 {%0,%1,%2,%3}, [%4];"
                 : "=r"(r0), "=r"(r1), "=r"(r2), "=r"(r3) : "r"(addr));
}
__device__ __forceinline__ void mma8(float* d, const uint32_t* a, const uint32_t* b) {
    asm volatile(
        "mma.sync.aligned.m16n8k8.row.col.f32.tf32.tf32.f32 "
        "{%0,%1,%2,%3}, {%4,%5,%6,%7}, {%8,%9}, {%0,%1,%2,%3};"
        : "+f"(d[0]), "+f"(d[1]), "+f"(d[2]), "+f"(d[3])
        : "r"(a[0]), "r"(a[1]), "r"(a[2]), "r"(a[3]), "r"(b[0]), "r"(b[1]));
}
__device__ __forceinline__ float silu(float g) {
    return g * (1.f / (1.f + __expf(-g)));
}

// ---------------- kernel 0: zero counts -------------------------------------
__global__ void zero_counts_kernel() {
    if (threadIdx.x < NEXP) g_count[threadIdx.x] = 0;
}

// ---------------- kernel 1: router + hidden pre-convert ----------------------
__global__ void router_kernel(const float* __restrict__ x,
                              const float* __restrict__ gw) {
    __shared__ float xs[HID];
    __shared__ float logits[NEXP];
    int t = blockIdx.x;
    const float* xp = x + (size_t)t * HID;
    for (int i = threadIdx.x; i < HID; i += blockDim.x) xs[i] = xp[i];
    __syncthreads();

    // pre-convert this token's row to RNA(lambda*x) while logits compute
    for (int i = threadIdx.x; i < HID; i += blockDim.x)
        ((uint32_t*)g_xcvt[t])[i] = cvt_tf32(LAMBDA * xs[i]);

    int warp = threadIdx.x >> 5, lane = threadIdx.x & 31;
    #pragma unroll
    for (int eo = 0; eo < 4; eo++) {
        int e = warp * 4 + eo;
        const float* w = gw + (size_t)e * HID;
        float s = 0.f;
        for (int j = lane; j < HID; j += 32) s += xs[j] * w[j];
        #pragma unroll
        for (int o = 16; o; o >>= 1) s += __shfl_xor_sync(0xffffffffu, s, o);
        if (lane == 0) logits[e] = s;
    }
    __syncthreads();

    if (threadIdx.x == 0) {
        float p[NEXP];
        float mx = -1e30f;
        #pragma unroll
        for (int e = 0; e < NEXP; e++) mx = fmaxf(mx, logits[e]);
        float sum = 0.f;
        #pragma unroll
        for (int e = 0; e < NEXP; e++) { p[e] = expf(logits[e] - mx); sum += p[e]; }
        float inv = 1.f / sum;
        #pragma unroll
        for (int e = 0; e < NEXP; e++) p[e] *= inv;

        float tv[TOPK]; int ti[TOPK];
        #pragma unroll
        for (int k = 0; k < TOPK; k++) {
            float best = -1.f; int bi = 0;
            #pragma unroll
            for (int e = 0; e < NEXP; e++)
                if (p[e] > best) { best = p[e]; bi = e; }
            tv[k] = best; ti[k] = bi; p[bi] = -1.f;
        }
        float s8 = 0.f;
        #pragma unroll
        for (int k = 0; k < TOPK; k++) s8 += tv[k];
        float invs8 = 1.f / fmaxf(s8, 1e-12f);
        float cum = 0.f; int cnt_lt = 0;
        #pragma unroll
        for (int k = 0; k < TOPK; k++) {
            cum += tv[k] * invs8;
            if (cum < THRESH) cnt_lt++;
        }
        int keep = min(cnt_lt + 1, TOPK);
        float ssel = 0.f;
        for (int k = 0; k < keep; k++) ssel += tv[k];
        float invsel = 1.f / fmaxf(ssel, 1e-12f);
        g_tok_nkeep[t] = keep;
        for (int k = 0; k < keep; k++) {
            int e = ti[k];
            int slot = atomicAdd(&g_count[e], 1);
            g_tokens[e][slot]   = t;
            g_tok_expert[t][k]  = e;
            g_tok_slot[t][k]    = slot;
            g_tok_w[t][k]       = tv[k] * invsel;
        }
    }
}

// ---------------- mma.sync tf32 grouped GEMM, 256thr x 2 CTAs/SM -------------
// 8 warps in 4(m) x 2(n); warp tile 32 x (32|64). A and B all via cp.async,
// 3-deep rings, single commit group + single __syncthreads per stage.
// B operands are RAW fp32 bits: the tf32 mma truncates low mantissa bits (RZ);
// the systematic truncation bias is compensated by LAMBDA pre-scaling of A.
// FUSED=true : BN=64 per matrix (gate+up), writes tf32 lambda*silu(g)*u to g_h.
// FUSED=false: BN=128, writes fp32 to g_downbuf.
template<bool FUSED>
__global__ __launch_bounds__(256, 2)
void moe_mma(const float* __restrict__ W) {
    constexpr int KDIM = FUSED ? HID : INTER_SZ;
    constexpr int NS   = KDIM / TK;              // 64 or 24
    constexpr int BNK  = FUSED ? 64 : 128;       // B rows per matrix tile
    constexpr int NJ   = FUSED ? 4 : 8;          // 8-col mma tiles per warp
    constexpr int NJ1  = FUSED ? 4 : 1;
    constexpr int WN   = FUSED ? 32 : 64;        // warp N extent
    constexpr int NB   = FUSED ? 2 : 4;          // B0 float4 chunks per thread

    const int e   = blockIdx.z;
    const int cnt = g_count[e];
    const int m0  = blockIdx.y * BM;
    if (m0 >= cnt) return;
    const int n0  = blockIdx.x * BNK;

    extern __shared__ float smf[];
    int*  toks = (int*)(smf + 27648);            // after A(3) + B(3) buffers

    const int tid  = threadIdx.x;
    const int lane = tid & 31, wid = tid >> 5;
    const int warp_m = wid & 3, warp_n = wid >> 2;           // 4 x 2 warps

    if (FUSED && tid < BM) {
        int r = m0 + tid;
        toks[tid] = (r < cnt) ? g_tokens[e][r] : g_tokens[e][0];
    }
    __syncthreads();

    const uint32_t sa  = smem_u32(smf);
    const uint32_t aAs = sa;                                 // A: [3][128][ROWF]
    const uint32_t aB0 = sa + 3 * BM * ROWF * 4;             // B0: [3][BNK][ROWF]
    const uint32_t aB1 = aB0 + 3 * BNK * ROWF * 4;           // B1 (FUSED): [3][64][ROWF]

    const float* Wb = W + (size_t)e * (FUSED ? (size_t)NGU * HID : (size_t)HID * INTER_SZ)
                        + (size_t)n0 * KDIM;
    const float* Wu = FUSED ? (W + (size_t)e * NGU * HID + (size_t)(INTER_SZ + n0) * HID)
                            : (const float*)nullptr;

    // per-thread ldsm base offsets (bytes within a buffer)
    const int grp = lane >> 3, rr = lane & 7;
    const uint32_t abase = (uint32_t)(((warp_m * 32 + (grp & 1) * 8 + rr) * ROWF
                                       + (grp >> 1) * 4) * 4);
    const uint32_t bbase = (uint32_t)(((warp_n * WN + (grp >> 1) * 8 + rr) * ROWF
                                       + (grp & 1) * 4) * 4);

    // ---- A + B staging via cp.async; 3-deep rings, one commit group/stage ----
    auto stage = [&](int s) {
        const int buf = s % 3;
        const int k0  = s * TK;
        const uint32_t bufA = aAs + buf * BM * ROWF * 4;
        #pragma unroll
        for (int i = 0; i < 4; i++) {                        // A: 1024 chunks / 256 thr
            int c = tid + i * 256; int row = c >> 3, q = c & 7;
            const float* src;
            if (FUSED) {
                src = &g_xcvt[toks[row]][k0 + q * 4];
            } else {
                int r = m0 + row; if (r >= cnt) r = m0;
                src = &g_h[e][r][k0 + q * 4];
            }
            cpasync16(bufA + (row * ROWF + q * 4) * 4, src);
        }
        const uint32_t bufB0 = aB0 + buf * BNK * ROWF * 4;
        #pragma unroll
        for (int i = 0; i < NB; i++) {                       // B0: BNK*8 chunks
            int c = tid + i * 256; int row = c >> 3, q = c & 7;
            cpasync16(bufB0 + (row * ROWF + q * 4) * 4,
                      Wb + (size_t)row * KDIM + k0 + q * 4);
        }
        if (FUSED) {
            const uint32_t bufB1 = aB1 + buf * 64 * ROWF * 4;
            #pragma unroll
            for (int i = 0; i < 2; i++) {                    // B1: 512 chunks
                int c = tid + i * 256; int row = c >> 3, q = c & 7;
                cpasync16(bufB1 + (row * ROWF + q * 4) * 4,
                          Wu + (size_t)row * KDIM + k0 + q * 4);
            }
        }
        asm volatile("cp.async.commit_group;" ::: "memory");
    };

    float acc0[2][NJ][4] = {};
    float acc1[2][NJ1][4] = {};

    // ---- prologue ----
    stage(0);
    stage(1);
    asm volatile("cp.async.wait_group 1;" ::: "memory");
    __syncthreads();

    for (int s = 0; s < NS; s++) {
        const uint32_t bufA  = aAs + (s % 3) * BM * ROWF * 4;
        const uint32_t bufB0 = aB0 + (s % 3) * BNK * ROWF * 4;
        const uint32_t bufB1 = aB1 + (s % 3) * 64 * ROWF * 4;

        #pragma unroll
        for (int kk = 0; kk < 4; kk++) {
            uint32_t a[2][4];
            #pragma unroll
            for (int i = 0; i < 2; i++)
                ldsm4(a[i][0], a[i][1], a[i][2], a[i][3],
                      bufA + abase + i * 16 * ROWF * 4 + kk * 32);
            uint32_t b0[NJ][2];
            #pragma unroll
            for (int jp = 0; jp < NJ / 2; jp++)
                ldsm4(b0[2 * jp][0], b0[2 * jp][1], b0[2 * jp + 1][0], b0[2 * jp + 1][1],
                      bufB0 + bbase + jp * 16 * ROWF * 4 + kk * 32);
            uint32_t b1[NJ1][2];
            if (FUSED) {
                #pragma unroll
                for (int jp = 0; jp < NJ1 / 2; jp++)
                    ldsm4(b1[2 * jp][0], b1[2 * jp][1], b1[2 * jp + 1][0], b1[2 * jp + 1][1],
                          bufB1 + bbase + jp * 16 * ROWF * 4 + kk * 32);
            }
            #pragma unroll
            for (int i = 0; i < 2; i++)
                #pragma unroll
                for (int j = 0; j < NJ; j++) {
                    mma8(acc0[i][j], a[i], b0[j]);
                    if (FUSED) mma8(acc1[i][j % NJ1], a[i], b1[j % NJ1]);
                }
        }

        // stage(s+2) targets ring slot (s+2)%3 = (s-1)%3, last read at stage
        // s-1 and fenced by the barrier that ended s-1. Single barrier/stage.
        if (s + 1 < NS) {
            if (s + 2 < NS) stage(s + 2);
            if (s + 2 < NS) asm volatile("cp.async.wait_group 1;" ::: "memory");
            else            asm volatile("cp.async.wait_group 0;" ::: "memory");
            __syncthreads();
        }
    }

    // ---- epilogue ----
    #pragma unroll
    for (int i = 0; i < 2; i++) {
        int r0 = m0 + warp_m * 32 + i * 16 + (lane >> 2);
        #pragma unroll
        for (int j = 0; j < NJ; j++) {
            int col = n0 + warp_n * WN + j * 8 + 2 * (lane & 3);
            if (FUSED) {
                if (r0 < cnt) {
                    float2 v;
                    v.x = __uint_as_float(cvt_tf32(LAMBDA * silu(acc0[i][j][0]) * acc1[i][j % NJ1][0]));
                    v.y = __uint_as_float(cvt_tf32(LAMBDA * silu(acc0[i][j][1]) * acc1[i][j % NJ1][1]));
                    *(float2*)&g_h[e][r0][col] = v;
                }
                if (r0 + 8 < cnt) {
                    float2 v;
                    v.x = __uint_as_float(cvt_tf32(LAMBDA * silu(acc0[i][j][2]) * acc1[i][j % NJ1][2]));
                    v.y = __uint_as_float(cvt_tf32(LAMBDA * silu(acc0[i][j][3]) * acc1[i][j % NJ1][3]));
                    *(float2*)&g_h[e][r0 + 8][col] = v;
                }
            } else {
                if (r0 < cnt) {
                    float2 v = make_float2(acc0[i][j][0], acc0[i][j][1]);
                    *(float2*)&g_downbuf[((size_t)e * T_TOKENS + r0) * HID + col] = v;
                }
                if (r0 + 8 < cnt) {
                    float2 v = make_float2(acc0[i][j][2], acc0[i][j][3]);
                    *(float2*)&g_downbuf[((size_t)e * T_TOKENS + r0 + 8) * HID + col] = v;
                }
            }
        }
    }
}

// ---------------- kernel 4: deterministic per-token combine -----------------
__global__ void combine_kernel(float* __restrict__ out) {
    int t = blockIdx.x;
    int nk = g_tok_nkeep[t];
    int   es[TOPK], ss[TOPK];
    float ws[TOPK];
    for (int k = 0; k < nk; k++) {
        es[k] = g_tok_expert[t][k];
        ss[k] = g_tok_slot[t][k];
        ws[k] = g_tok_w[t][k];
    }
    for (int h = threadIdx.x * 4; h < HID; h += blockDim.x * 4) {
        float4 acc = make_float4(0.f, 0.f, 0.f, 0.f);
        for (int k = 0; k < nk; k++) {
            const float4 v = *(const float4*)
                &g_downbuf[((size_t)es[k] * T_TOKENS + ss[k]) * HID + h];
            acc.x += ws[k] * v.x; acc.y += ws[k] * v.y;
            acc.z += ws[k] * v.z; acc.w += ws[k] * v.w;
        }
        *(float4*)&out[(size_t)t * HID + h] = acc;
    }
}

// ---------------- launch ----------------------------------------------------
// A(3x128 rows) + B(3x128 rows total) = 768 rows * ROWF floats = 27648 floats
#define SMEM_BYTES (27648 * 4 + BM * 4)   // 111104 B; 2 CTAs/SM (222KB < 228KB)

extern "C" void kernel_launch(void* const* d_in, const int* in_sizes, int n_in,
                              void* d_out, int out_size) {
    const float* hidden  = (const float*)d_in[0];   // [2,1024,2048]
    const float* gate_w  = (const float*)d_in[1];   // [32,2048]
    const float* gate_up = (const float*)d_in[2];   // [32,1536,2048]
    const float* down_w  = (const float*)d_in[3];   // [32,2048,768]
    float* out = (float*)d_out;

    cudaFuncSetAttribute(moe_mma<true>,  cudaFuncAttributeMaxDynamicSharedMemorySize, SMEM_BYTES);
    cudaFuncSetAttribute(moe_mma<false>, cudaFuncAttributeMaxDynamicSharedMemorySize, SMEM_BYTES);

    zero_counts_kernel<<<1, 32>>>();
    router_kernel<<<T_TOKENS, 256>>>(hidden, gate_w);
    {
        dim3 grid(INTER_SZ / 64, T_TOKENS / BM, NEXP);    // (12, 16, 32)
        moe_mma<true><<<grid, 256, SMEM_BYTES>>>(gate_up);
    }
    {
        dim3 grid(HID / 128, T_TOKENS / BM, NEXP);        // (16, 16, 32)
        moe_mma<false><<<grid, 256, SMEM_BYTES>>>(down_w);
    }
    combine_kernel<<<T_TOKENS, 256>>>(out);
}

// round 14
// speedup vs baseline: 2.1586x; 1.0295x over previous
#include <cuda_runtime.h>
#include <math.h>
#include <stdint.h>

#define T_TOKENS 2048
#define HID 2048
#define NEXP 32
#define TOPK 8
#define INTER_SZ 768
#define NGU 1536
#define THRESH 0.8f
#define LAMBDA 1.000345f   // compensation for tf32 RZ-truncation of B operands

#define BM 64
#define TK 32
#define ROWF 36   // padded floats per smem row (32 + 4); 144B row stride

// ---------------- scratch (static device globals; no allocation) -------------
__device__ int   g_count[NEXP];
__device__ int   g_tokens[NEXP][T_TOKENS];
__device__ int   g_tok_nkeep[T_TOKENS];
__device__ int   g_tok_expert[T_TOKENS][TOPK];
__device__ int   g_tok_slot[T_TOKENS][TOPK];
__device__ float g_tok_w[T_TOKENS][TOPK];
__device__ __align__(128) float g_xcvt[T_TOKENS][HID];                 // RNA(lambda * x)
__device__ __align__(128) float g_h[NEXP][T_TOKENS][INTER_SZ];        // RNA(lambda * silu(g)*u)
__device__ __align__(128) float g_downbuf[(size_t)NEXP * T_TOKENS * HID];

// ---------------- helpers ----------------------------------------------------
__device__ __forceinline__ uint32_t cvt_tf32(float f) {
    uint32_t r;
    asm("cvt.rna.tf32.f32 %0, %1;" : "=r"(r) : "f"(f));
    return r;
}
__device__ __forceinline__ void cpasync16(uint32_t dst, const void* src) {
    asm volatile("cp.async.cg.shared.global [%0], [%1], 16;" :: "r"(dst), "l"(src));
}
__device__ __forceinline__ uint32_t smem_u32(const void* p) {
    uint32_t a;
    asm("{ .reg .u64 t; cvta.to.shared.u64 t, %1; cvt.u32.u64 %0, t; }" : "=r"(a) : "l"(p));
    return a;
}
__device__ __forceinline__ void ldsm4(uint32_t& r0, uint32_t& r1, uint32_t& r2, uint32_t& r3,
                                      uint32_t addr) {
    asm volatile("ldmatrix.sync.aligned.m8n8.x4.shared.b16 {%0,%1,%2,%3}, [%4];"
                 : "=r"(r0), "=r"(r1), "=r"(r2), "=r"(r3) : "r"(addr));
}
__device__ __forceinline__ void mma8(float* d, const uint32_t* a, const uint32_t* b) {
    asm volatile(
        "mma.sync.aligned.m16n8k8.row.col.f32.tf32.tf32.f32 "
        "{%0,%1,%2,%3}, {%4,%5,%6,%7}, {%8,%9}, {%0,%1,%2,%3};"
        : "+f"(d[0]), "+f"(d[1]), "+f"(d[2]), "+f"(d[3])
        : "r"(a[0]), "r"(a[1]), "r"(a[2]), "r"(a[3]), "r"(b[0]), "r"(b[1]));
}
__device__ __forceinline__ float silu(float g) {
    return g * (1.f / (1.f + __expf(-g)));
}

// ---------------- kernel 0: zero counts -------------------------------------
__global__ void zero_counts_kernel() {
    if (threadIdx.x < NEXP) g_count[threadIdx.x] = 0;
}

// ---------------- kernel 1: router + hidden pre-convert ----------------------
__global__ void router_kernel(const float* __restrict__ x,
                              const float* __restrict__ gw) {
    __shared__ float xs[HID];
    __shared__ float logits[NEXP];
    int t = blockIdx.x;
    const float* xp = x + (size_t)t * HID;
    for (int i = threadIdx.x; i < HID; i += blockDim.x) xs[i] = xp[i];
    __syncthreads();

    // pre-convert this token's row to RNA(lambda*x) while logits compute
    for (int i = threadIdx.x; i < HID; i += blockDim.x)
        ((uint32_t*)g_xcvt[t])[i] = cvt_tf32(LAMBDA * xs[i]);

    int warp = threadIdx.x >> 5, lane = threadIdx.x & 31;
    #pragma unroll
    for (int eo = 0; eo < 4; eo++) {
        int e = warp * 4 + eo;
        const float* w = gw + (size_t)e * HID;
        float s = 0.f;
        for (int j = lane; j < HID; j += 32) s += xs[j] * w[j];
        #pragma unroll
        for (int o = 16; o; o >>= 1) s += __shfl_xor_sync(0xffffffffu, s, o);
        if (lane == 0) logits[e] = s;
    }
    __syncthreads();

    if (threadIdx.x == 0) {
        float p[NEXP];
        float mx = -1e30f;
        #pragma unroll
        for (int e = 0; e < NEXP; e++) mx = fmaxf(mx, logits[e]);
        float sum = 0.f;
        #pragma unroll
        for (int e = 0; e < NEXP; e++) { p[e] = expf(logits[e] - mx); sum += p[e]; }
        float inv = 1.f / sum;
        #pragma unroll
        for (int e = 0; e < NEXP; e++) p[e] *= inv;

        float tv[TOPK]; int ti[TOPK];
        #pragma unroll
        for (int k = 0; k < TOPK; k++) {
            float best = -1.f; int bi = 0;
            #pragma unroll
            for (int e = 0; e < NEXP; e++)
                if (p[e] > best) { best = p[e]; bi = e; }
            tv[k] = best; ti[k] = bi; p[bi] = -1.f;
        }
        float s8 = 0.f;
        #pragma unroll
        for (int k = 0; k < TOPK; k++) s8 += tv[k];
        float invs8 = 1.f / fmaxf(s8, 1e-12f);
        float cum = 0.f; int cnt_lt = 0;
        #pragma unroll
        for (int k = 0; k < TOPK; k++) {
            cum += tv[k] * invs8;
            if (cum < THRESH) cnt_lt++;
        }
        int keep = min(cnt_lt + 1, TOPK);
        float ssel = 0.f;
        for (int k = 0; k < keep; k++) ssel += tv[k];
        float invsel = 1.f / fmaxf(ssel, 1e-12f);
        g_tok_nkeep[t] = keep;
        for (int k = 0; k < keep; k++) {
            int e = ti[k];
            int slot = atomicAdd(&g_count[e], 1);
            g_tokens[e][slot]   = t;
            g_tok_expert[t][k]  = e;
            g_tok_slot[t][k]    = slot;
            g_tok_w[t][k]       = tv[k] * invsel;
        }
    }
}

// ---------------- mma.sync tf32 grouped GEMM, 128thr x 4 CTAs/SM -------------
// 4 warps in 2(m) x 2(n); warp tile 32 x (32|64); BM=64 (halves tile padding).
// 2-deep rings, two barriers per stage (R8 scheme) -- the 4 co-resident CTAs
// provide the cross-CTA overlap that hides barrier/wait exposure.
// B operands are RAW fp32 bits (tf32 mma truncates, compensated by LAMBDA
// pre-scaling of A). FUSED=true: BN=64/matrix (gate+up) -> tf32 g_h.
// FUSED=false: BN=128 -> fp32 g_downbuf.
template<bool FUSED>
__global__ __launch_bounds__(128, 4)
void moe_mma(const float* __restrict__ W) {
    constexpr int KDIM = FUSED ? HID : INTER_SZ;
    constexpr int NS   = KDIM / TK;              // 64 or 24
    constexpr int BNK  = FUSED ? 64 : 128;       // B0 rows per tile
    constexpr int NJ   = FUSED ? 4 : 8;          // 8-col mma tiles per warp
    constexpr int NJ1  = FUSED ? 4 : 1;
    constexpr int WN   = FUSED ? 32 : 64;        // warp N extent
    constexpr int NA   = 4;                      // A chunks/thread (64*8/128)
    constexpr int NB0  = BNK * 8 / 128;          // 4 or 8
    constexpr int BROWS = 128;                   // total B rows staged (B0[+B1])

    const int e   = blockIdx.z;
    const int cnt = g_count[e];
    const int m0  = blockIdx.y * BM;
    if (m0 >= cnt) return;
    const int n0  = blockIdx.x * BNK;

    extern __shared__ float smf[];
    int*  toks = (int*)(smf + 2 * (BM + BROWS) * ROWF);

    const int tid  = threadIdx.x;
    const int lane = tid & 31, wid = tid >> 5;
    const int warp_m = wid & 1, warp_n = wid >> 1;           // 2 x 2 warps

    if (FUSED && tid < BM) {
        int r = m0 + tid;
        toks[tid] = (r < cnt) ? g_tokens[e][r] : g_tokens[e][0];
    }
    __syncthreads();

    const uint32_t sa  = smem_u32(smf);
    const uint32_t aAs = sa;                                 // A: [2][64][ROWF]
    const uint32_t aB0 = sa + 2 * BM * ROWF * 4;             // B0: [2][BNK][ROWF]
    const uint32_t aB1 = aB0 + 2 * BNK * ROWF * 4;           // B1 (FUSED): [2][64][ROWF]

    const float* Wb = W + (size_t)e * (FUSED ? (size_t)NGU * HID : (size_t)HID * INTER_SZ)
                        + (size_t)n0 * KDIM;
    const float* Wu = FUSED ? (W + (size_t)e * NGU * HID + (size_t)(INTER_SZ + n0) * HID)
                            : (const float*)nullptr;

    // per-thread ldsm base offsets (bytes within a buffer)
    const int grp = lane >> 3, rr = lane & 7;
    const uint32_t abase = (uint32_t)(((warp_m * 32 + (grp & 1) * 8 + rr) * ROWF
                                       + (grp >> 1) * 4) * 4);
    const uint32_t bbase = (uint32_t)(((warp_n * WN + (grp >> 1) * 8 + rr) * ROWF
                                       + (grp & 1) * 4) * 4);

    // ---- A + B staging via cp.async; 2-deep rings, one commit group/stage ----
    auto stage = [&](int s) {
        const int buf = s & 1;
        const int k0  = s * TK;
        const uint32_t bufA = aAs + buf * BM * ROWF * 4;
        #pragma unroll
        for (int i = 0; i < NA; i++) {                       // A: 512 chunks / 128 thr
            int c = tid + i * 128; int row = c >> 3, q = c & 7;
            const float* src;
            if (FUSED) {
                src = &g_xcvt[toks[row]][k0 + q * 4];
            } else {
                int r = m0 + row; if (r >= cnt) r = m0;
                src = &g_h[e][r][k0 + q * 4];
            }
            cpasync16(bufA + (row * ROWF + q * 4) * 4, src);
        }
        const uint32_t bufB0 = aB0 + buf * BNK * ROWF * 4;
        #pragma unroll
        for (int i = 0; i < NB0; i++) {                      // B0: BNK*8 chunks
            int c = tid + i * 128; int row = c >> 3, q = c & 7;
            cpasync16(bufB0 + (row * ROWF + q * 4) * 4,
                      Wb + (size_t)row * KDIM + k0 + q * 4);
        }
        if (FUSED) {
            const uint32_t bufB1 = aB1 + buf * 64 * ROWF * 4;
            #pragma unroll
            for (int i = 0; i < 4; i++) {                    // B1: 512 chunks
                int c = tid + i * 128; int row = c >> 3, q = c & 7;
                cpasync16(bufB1 + (row * ROWF + q * 4) * 4,
                          Wu + (size_t)row * KDIM + k0 + q * 4);
            }
        }
        asm volatile("cp.async.commit_group;" ::: "memory");
    };

    float acc0[2][NJ][4] = {};
    float acc1[2][NJ1][4] = {};

    // ---- prologue ----
    stage(0);
    stage(1);

    for (int s = 0; s < NS; s++) {
        if (s + 1 < NS) asm volatile("cp.async.wait_group 1;" ::: "memory");
        else            asm volatile("cp.async.wait_group 0;" ::: "memory");
        __syncthreads();

        const uint32_t bufA  = aAs + (s & 1) * BM * ROWF * 4;
        const uint32_t bufB0 = aB0 + (s & 1) * BNK * ROWF * 4;
        const uint32_t bufB1 = aB1 + (s & 1) * 64 * ROWF * 4;

        #pragma unroll
        for (int kk = 0; kk < 4; kk++) {
            uint32_t a[2][4];
            #pragma unroll
            for (int i = 0; i < 2; i++)
                ldsm4(a[i][0], a[i][1], a[i][2], a[i][3],
                      bufA + abase + i * 16 * ROWF * 4 + kk * 32);
            uint32_t b0[NJ][2];
            #pragma unroll
            for (int jp = 0; jp < NJ / 2; jp++)
                ldsm4(b0[2 * jp][0], b0[2 * jp][1], b0[2 * jp + 1][0], b0[2 * jp + 1][1],
                      bufB0 + bbase + jp * 16 * ROWF * 4 + kk * 32);
            uint32_t b1[NJ1][2];
            if (FUSED) {
                #pragma unroll
                for (int jp = 0; jp < NJ1 / 2; jp++)
                    ldsm4(b1[2 * jp][0], b1[2 * jp][1], b1[2 * jp + 1][0], b1[2 * jp + 1][1],
                          bufB1 + bbase + jp * 16 * ROWF * 4 + kk * 32);
            }
            #pragma unroll
            for (int i = 0; i < 2; i++)
                #pragma unroll
                for (int j = 0; j < NJ; j++) {
                    mma8(acc0[i][j], a[i], b0[j]);
                    if (FUSED) mma8(acc1[i][j % NJ1], a[i], b1[j % NJ1]);
                }
        }

        // second barrier: all reads of buf s&1 done; stage(s+2) may overwrite it
        __syncthreads();
        if (s + 2 < NS) stage(s + 2);
    }

    // ---- epilogue ----
    #pragma unroll
    for (int i = 0; i < 2; i++) {
        int r0 = m0 + warp_m * 32 + i * 16 + (lane >> 2);
        #pragma unroll
        for (int j = 0; j < NJ; j++) {
            int col = n0 + warp_n * WN + j * 8 + 2 * (lane & 3);
            if (FUSED) {
                if (r0 < cnt) {
                    float2 v;
                    v.x = __uint_as_float(cvt_tf32(LAMBDA * silu(acc0[i][j][0]) * acc1[i][j % NJ1][0]));
                    v.y = __uint_as_float(cvt_tf32(LAMBDA * silu(acc0[i][j][1]) * acc1[i][j % NJ1][1]));
                    *(float2*)&g_h[e][r0][col] = v;
                }
                if (r0 + 8 < cnt) {
                    float2 v;
                    v.x = __uint_as_float(cvt_tf32(LAMBDA * silu(acc0[i][j][2]) * acc1[i][j % NJ1][2]));
                    v.y = __uint_as_float(cvt_tf32(LAMBDA * silu(acc0[i][j][3]) * acc1[i][j % NJ1][3]));
                    *(float2*)&g_h[e][r0 + 8][col] = v;
                }
            } else {
                if (r0 < cnt) {
                    float2 v = make_float2(acc0[i][j][0], acc0[i][j][1]);
                    *(float2*)&g_downbuf[((size_t)e * T_TOKENS + r0) * HID + col] = v;
                }
                if (r0 + 8 < cnt) {
                    float2 v = make_float2(acc0[i][j][2], acc0[i][j][3]);
                    *(float2*)&g_downbuf[((size_t)e * T_TOKENS + r0 + 8) * HID + col] = v;
                }
            }
        }
    }
}

// ---------------- kernel 4: deterministic per-token combine -----------------
__global__ void combine_kernel(float* __restrict__ out) {
    int t = blockIdx.x;
    int nk = g_tok_nkeep[t];
    int   es[TOPK], ss[TOPK];
    float ws[TOPK];
    for (int k = 0; k < nk; k++) {
        es[k] = g_tok_expert[t][k];
        ss[k] = g_tok_slot[t][k];
        ws[k] = g_tok_w[t][k];
    }
    for (int h = threadIdx.x * 4; h < HID; h += blockDim.x * 4) {
        float4 acc = make_float4(0.f, 0.f, 0.f, 0.f);
        for (int k = 0; k < nk; k++) {
            const float4 v = *(const float4*)
                &g_downbuf[((size_t)es[k] * T_TOKENS + ss[k]) * HID + h];
            acc.x += ws[k] * v.x; acc.y += ws[k] * v.y;
            acc.z += ws[k] * v.z; acc.w += ws[k] * v.w;
        }
        *(float4*)&out[(size_t)t * HID + h] = acc;
    }
}

// ---------------- launch ----------------------------------------------------
// 2 rings x (A 64 + B 128 rows) x ROWF floats = 13824 floats + 64 toks
#define SMEM_BYTES (2 * (64 + 128) * ROWF * 4 + 64 * 4)   // 55552 B; 4 CTAs/SM

extern "C" void kernel_launch(void* const* d_in, const int* in_sizes, int n_in,
                              void* d_out, int out_size) {
    const float* hidden  = (const float*)d_in[0];   // [2,1024,2048]
    const float* gate_w  = (const float*)d_in[1];   // [32,2048]
    const float* gate_up = (const float*)d_in[2];   // [32,1536,2048]
    const float* down_w  = (const float*)d_in[3];   // [32,2048,768]
    float* out = (float*)d_out;

    cudaFuncSetAttribute(moe_mma<true>,  cudaFuncAttributeMaxDynamicSharedMemorySize, SMEM_BYTES);
    cudaFuncSetAttribute(moe_mma<false>, cudaFuncAttributeMaxDynamicSharedMemorySize, SMEM_BYTES);

    zero_counts_kernel<<<1, 32>>>();
    router_kernel<<<T_TOKENS, 256>>>(hidden, gate_w);
    {
        dim3 grid(INTER_SZ / 64, T_TOKENS / BM, NEXP);    // (12, 32, 32)
        moe_mma<true><<<grid, 128, SMEM_BYTES>>>(gate_up);
    }
    {
        dim3 grid(HID / 128, T_TOKENS / BM, NEXP);        // (16, 32, 32)
        moe_mma<false><<<grid, 128, SMEM_BYTES>>>(down_w);
    }
    combine_kernel<<<T_TOKENS, 256>>>(out);
}